// round 5
// baseline (speedup 1.0000x reference)
#include <cuda_runtime.h>
#include <math.h>

#define NQ 10
#define NP 100
#define FD 256
#define NOUT 30
#define TWO_PI_F 6.2831853071795864769f

// Cross-CTA scratch + per-sample arrival counters (zero-init; restored to 0
// by the combining warp each launch, so graph replays see a clean state).
__device__ float g_mres[3][256][32];
__device__ int   g_cnt[256];

__device__ __forceinline__ float bfly(float v) {
#pragma unroll
    for (int o = 16; o; o >>= 1) v += __shfl_xor_sync(0xffffffffu, v, o);
    return v;
}

// ---------------------------------------------------------------------------
// One WARP = one (sample, branch) circuit. amp = (j << 5) | lane.
// amp bits [4:0] = lane (gates via shfl_xor), bits [9:5] = j (register-local).
// sr/si[32] fully unrolled -> stays in registers. Zero barriers in the chain.
// ---------------------------------------------------------------------------

// Fused SU(2) gate on amp-bit b. U = [[u00,u01],[-conj(u01),conj(u00)]]
__device__ __forceinline__ void u1q(int b, float u00r, float u00i,
                                    float u01r, float u01i,
                                    float sr[32], float si[32], int lane) {
    if (b >= 5) {                                 // local bit
        const int lb = b - 5;
        const int lm = (1 << lb) - 1;
#pragma unroll
        for (int t = 0; t < 16; t++) {
            const int j0 = ((t & ~lm) << 1) | (t & lm);
            const int j1 = j0 | (1 << lb);
            float r0 = sr[j0], i0 = si[j0], r1 = sr[j1], i1 = si[j1];
            sr[j0] =  u00r * r0 - u00i * i0 + u01r * r1 - u01i * i1;
            si[j0] =  u00r * i0 + u00i * r0 + u01r * i1 + u01i * r1;
            sr[j1] = -u01r * r0 - u01i * i0 + u00r * r1 + u00i * i1;
            si[j1] = -u01r * i0 + u01i * r0 + u00r * i1 - u00i * r1;
        }
    } else {                                      // lane bit: shuffles
        const int m = 1 << b;
        const int s = (lane >> b) & 1;
        const float cwr = u00r, cwi = s ? -u00i : u00i;
        const float cpr = s ? -u01r : u01r, cpi = u01i;
#pragma unroll
        for (int j = 0; j < 32; j++) {
            float pr = __shfl_xor_sync(0xffffffffu, sr[j], m);
            float pi = __shfl_xor_sync(0xffffffffu, si[j], m);
            float orr = sr[j], oii = si[j];
            sr[j] = cwr * orr - cwi * oii + cpr * pr - cpi * pi;
            si[j] = cwr * oii + cwi * orr + cpr * pi + cpi * pr;
        }
    }
}

// Controlled-RX, control bit pc, target bit pt (distinct).
__device__ __forceinline__ void crx(int pc, int pt, float c, float s,
                                    float sr[32], float si[32], int lane) {
    if (pt >= 5) {                                // local target
        const int lt = pt - 5;
        const int lm = (1 << lt) - 1;
        if (pc >= 5) {                            // local control: prune pairs
            const int cm = 1 << (pc - 5);
#pragma unroll
            for (int t = 0; t < 16; t++) {
                const int j0 = ((t & ~lm) << 1) | (t & lm);
                const int j1 = j0 | (1 << lt);
                if (j0 & cm) {
                    float r0 = sr[j0], i0 = si[j0], r1 = sr[j1], i1 = si[j1];
                    sr[j0] = c * r0 + s * i1;  si[j0] = c * i0 - s * r1;
                    sr[j1] = c * r1 + s * i0;  si[j1] = c * i1 - s * r0;
                }
            }
        } else {                                  // lane control: predicated
            const bool tc = ((lane >> pc) & 1) != 0;
#pragma unroll
            for (int t = 0; t < 16; t++) {
                const int j0 = ((t & ~lm) << 1) | (t & lm);
                const int j1 = j0 | (1 << lt);
                if (tc) {
                    float r0 = sr[j0], i0 = si[j0], r1 = sr[j1], i1 = si[j1];
                    sr[j0] = c * r0 + s * i1;  si[j0] = c * i0 - s * r1;
                    sr[j1] = c * r1 + s * i0;  si[j1] = c * i1 - s * r0;
                }
            }
        }
    } else {                                      // lane target: shuffles
        const int m = 1 << pt;
        if (pc >= 5) {                            // local control: half the j's
            const int cm = 1 << (pc - 5);
#pragma unroll
            for (int j = 0; j < 32; j++) {
                if (j & cm) {
                    float pr = __shfl_xor_sync(0xffffffffu, sr[j], m);
                    float pi = __shfl_xor_sync(0xffffffffu, si[j], m);
                    float orr = sr[j], oii = si[j];
                    sr[j] = c * orr + s * pi;
                    si[j] = c * oii - s * pr;
                }
            }
        } else {                                  // lane control: predicated
            const bool tc = ((lane >> pc) & 1) != 0;
#pragma unroll
            for (int j = 0; j < 32; j++) {
                float pr = __shfl_xor_sync(0xffffffffu, sr[j], m);
                float pi = __shfl_xor_sync(0xffffffffu, si[j], m);
                if (tc) {
                    float orr = sr[j], oii = si[j];
                    sr[j] = c * orr + s * pi;
                    si[j] = c * oii - s * pr;
                }
            }
        }
    }
}

__global__ __launch_bounds__(128, 2)
void qsb_warp_kernel(const float* __restrict__ x,
                     const float* __restrict__ W1, const float* __restrict__ b1,
                     const float* __restrict__ W2, const float* __restrict__ b2,
                     const float* __restrict__ W3, const float* __restrict__ b3,
                     const float* __restrict__ base1, const float* __restrict__ base2,
                     const float* __restrict__ base3,
                     const float* __restrict__ alpha_r, const float* __restrict__ alpha_i,
                     const float* __restrict__ beta_r,  const float* __restrict__ beta_i,
                     const float* __restrict__ gamma_r, const float* __restrict__ gamma_i,
                     float* __restrict__ out) {
    __shared__ float gcs[4][NP], gss[4][NP];

    const int tid    = threadIdx.x;
    const int warp   = tid >> 5;
    const int lane   = tid & 31;
    const int branch = blockIdx.x >> 6;           // 64 CTAs per branch
    const int batch  = ((blockIdx.x & 63) << 2) | warp;

    const float* W  = (branch == 0) ? W1 : ((branch == 1) ? W2 : W3);
    const float* bb = (branch == 0) ? b1 : ((branch == 1) ? b2 : b3);
    const float* ba = (branch == 0) ? base1 : ((branch == 1) ? base2 : base3);

    // ---- GEMV: warp computes all 100 rows for its own sample ----
    {
        const float4* xv = (const float4*)(x + batch * FD);
        const float4 x0 = xv[lane * 2];
        const float4 x1 = xv[lane * 2 + 1];
        const float4* Wv = (const float4*)W;
#pragma unroll 2
        for (int p = 0; p < NP; p++) {
            float4 w0 = Wv[p * 64 + lane * 2];
            float4 w1 = Wv[p * 64 + lane * 2 + 1];
            float acc = w0.x * x0.x + w0.y * x0.y + w0.z * x0.z + w0.w * x0.w
                      + w1.x * x1.x + w1.y * x1.y + w1.z * x1.z + w1.w * x1.w;
            acc = bfly(acc);
            if (lane == 0) gcs[warp][p] = acc;
        }
        __syncwarp();
        for (int k = lane; k < NP; k += 32) {     // lane-parallel transcendentals
            float t     = gcs[warp][k] + bb[k] + ba[k];
            float sig   = 1.f / (1.f + __expf(-t));
            float sv, cv;
            __sincosf(0.5f * sig * TWO_PI_F, &sv, &cv);
            gcs[warp][k] = cv; gss[warp][k] = sv;
        }
        __syncwarp();
    }

    // ---- statevector: 32 complex amps per lane, all in registers ----
    float sr[32], si[32];
#pragma unroll
    for (int j = 0; j < 32; j++) { sr[j] = 0.f; si[j] = 0.f; }
    if (lane == 0) sr[0] = 1.f;

#pragma unroll
    for (int layer = 0; layer < 2; layer++) {
        const int base = layer * 50;
#pragma unroll
        for (int w = 0; w < NQ; w++) {
            float c0 = gcs[warp][base + 3 * w],     s0 = gss[warp][base + 3 * w];
            float c1 = gcs[warp][base + 3 * w + 1], s1 = gss[warp][base + 3 * w + 1];
            float cz = gcs[warp][base + 3 * w + 2], sz = gss[warp][base + 3 * w + 2];
            // Fused U = Rz*Ry*Rx
            float u00r =  cz * c1 * c0 + sz * s1 * s0;
            float u00i =  cz * s1 * s0 - sz * c1 * c0;
            float u01r = -(cz * s1 * c0 + sz * c1 * s0);
            float u01i =  sz * s1 * c0 - cz * c1 * s0;
            u1q(9 - w, u00r, u00i, u01r, u01i, sr, si, lane);
        }
#pragma unroll
        for (int i = 0; i < NQ; i++)
            crx(9 - i, 9 - ((i + 1) % NQ),
                gcs[warp][base + 30 + i], gss[warp][base + 30 + i], sr, si, lane);
#pragma unroll
        for (int i = NQ - 1; i >= 0; i--)
            crx(9 - i, 9 - ((i + 9) % NQ),
                gcs[warp][base + 40 + (9 - i)], gss[warp][base + 40 + (9 - i)],
                sr, si, lane);
    }

    // ---- expectations <X>,<Y>,<Z> per wire; lane k<30 collects output k ----
    float myout = 0.f;
#pragma unroll
    for (int w = 0; w < NQ; w++) {
        const int p = 9 - w;
        float zr = 0.f, zi = 0.f, pz = 0.f;
        if (p >= 5) {                             // local bit pairs
            const int lt = p - 5;
            const int lm = (1 << lt) - 1;
#pragma unroll
            for (int t = 0; t < 16; t++) {
                const int j0 = ((t & ~lm) << 1) | (t & lm);
                const int j1 = j0 | (1 << lt);
                float r0 = sr[j0], i0 = si[j0], r1 = sr[j1], i1 = si[j1];
                zr += r0 * r1 + i0 * i1;
                zi += r0 * i1 - i0 * r1;
                pz += (r0 * r0 + i0 * i0) - (r1 * r1 + i1 * i1);
            }
        } else {                                  // lane bit pairs
            const int m  = 1 << p;
            const bool hi = ((lane >> p) & 1) != 0;
            const float sgn = hi ? -1.f : 1.f;
#pragma unroll
            for (int j = 0; j < 32; j++) {
                float pr = __shfl_xor_sync(0xffffffffu, sr[j], m);
                float pi = __shfl_xor_sync(0xffffffffu, si[j], m);
                if (!hi) {
                    zr += sr[j] * pr + si[j] * pi;
                    zi += sr[j] * pi - si[j] * pr;
                }
                pz += sgn * (sr[j] * sr[j] + si[j] * si[j]);
            }
        }
        zr = bfly(zr); zi = bfly(zi); pz = bfly(pz);
        if (lane == w)           myout = 2.f * zr;
        if (lane == NQ + w)      myout = 2.f * zi;
        if (lane == 2 * NQ + w)  myout = pz;
    }

    if (lane < NOUT) g_mres[branch][batch][lane] = myout;
    __threadfence();
    int old = 0;
    if (lane == 0) old = atomicAdd(&g_cnt[batch], 1);
    old = __shfl_sync(0xffffffffu, old, 0);

    if (old == 2) {                               // last branch-warp combines
        __threadfence();
        float arv = alpha_r[0], aiv = alpha_i[0];
        float brv = beta_r[0],  biv = beta_i[0];
        float grv = gamma_r[0], giv = gamma_i[0];
        float nrm = sqrtf(arv * arv + aiv * aiv + brv * brv + biv * biv +
                          grv * grv + giv * giv + 1e-9f);
        float inv = 1.f / nrm;
        if (lane < NOUT) {
            float m0 = g_mres[0][batch][lane];
            float m1 = g_mres[1][batch][lane];
            float m2 = g_mres[2][batch][lane];
            float re = (arv * m0 + brv * m1 + grv * m2) * inv;
            float im = (aiv * m0 + biv * m1 + giv * m2) * inv;
            out[batch * NOUT + lane] = sqrtf(re * re + im * im);
        }
        if (lane == 0) g_cnt[batch] = 0;          // restore for next replay
    }
}

extern "C" void kernel_launch(void* const* d_in, const int* in_sizes, int n_in,
                              void* d_out, int out_size) {
    const float* x      = (const float*)d_in[0];
    const float* W1     = (const float*)d_in[1];
    const float* b1     = (const float*)d_in[2];
    const float* W2     = (const float*)d_in[3];
    const float* b2     = (const float*)d_in[4];
    const float* W3     = (const float*)d_in[5];
    const float* b3     = (const float*)d_in[6];
    const float* base1  = (const float*)d_in[7];
    const float* base2  = (const float*)d_in[8];
    const float* base3  = (const float*)d_in[9];
    const float* ar     = (const float*)d_in[10];
    const float* ai     = (const float*)d_in[11];
    const float* br     = (const float*)d_in[12];
    const float* bi     = (const float*)d_in[13];
    const float* gr     = (const float*)d_in[14];
    const float* gi     = (const float*)d_in[15];
    float* out = (float*)d_out;

    // 192 CTAs x 128 threads = 768 warps = 256 samples x 3 branches
    qsb_warp_kernel<<<192, 128>>>(x, W1, b1, W2, b2, W3, b3,
                                  base1, base2, base3,
                                  ar, ai, br, bi, gr, gi, out);
}